// round 1
// baseline (speedup 1.0000x reference)
#include <cuda_runtime.h>
#include <math.h>

#define NN 35000
#define NM 80000
#define NBR 6
#define IND 128
#define HD 256
#define DEPTH 5

#define BM 64
#define BN 64
#define BK 16

// Scratch (allocation-free rule: __device__ globals)
__device__ float g_rx2 [(size_t)NM*HD];
__device__ float g_fz  [(size_t)NM*HD];
__device__ float g_fh  [(size_t)NM*HD];
__device__ float g_hU  [(size_t)NM*HD];
__device__ float g_sumh[(size_t)NM*HD];
__device__ float g_sumg[(size_t)NM*HD];
__device__ float g_hA  [(size_t)NM*HD];
__device__ float g_nei [(size_t)NN*HD];

__device__ __forceinline__ float sigm(float x){ return 1.0f/(1.0f+expf(-x)); }

// Dual-GEMM: acc1 = A1[M,K1]@B1[K1,256], acc2 = A2[M,K2]@B2[K2,256]
// All A row-major ld=K, all B row-major ld=256.
// MODE 0: C = acc1 + bias(e0)            (single GEMM)
// MODE 1: GRU step epilogue (e0=fz, e1=fh, e2=sum_h)
// MODE 2: C = relu(acc1+acc2+e0[n]) * e2[row]   (output layer)
template<int MODE>
__global__ __launch_bounds__(256)
void dual_gemm(const float* __restrict__ A1, int K1, const float* __restrict__ B1,
               const float* __restrict__ A2, int K2, const float* __restrict__ B2,
               int M,
               const float* __restrict__ e0, const float* __restrict__ e1,
               const float* __restrict__ e2, float* __restrict__ C)
{
    __shared__ float As[BK][BM];
    __shared__ float Bs[BK][BN];
    const int tid = threadIdx.x;
    const int tx = tid & 15, ty = tid >> 4;
    const int rowBase = blockIdx.y * BM;
    const int colBase = blockIdx.x * BN;
    const int a_row = tid >> 2,  a_col = (tid & 3)  << 2;
    const int b_row = tid >> 4,  b_col = (tid & 15) << 2;
    const int grow = rowBase + a_row;

    float acc1[16], acc2[16];
    #pragma unroll
    for (int i = 0; i < 16; ++i) { acc1[i] = 0.f; acc2[i] = 0.f; }

#define GEMM_PHASE(A, K, B, acc)                                                   \
    for (int k0 = 0; k0 < (K); k0 += BK) {                                         \
        float4 av = make_float4(0.f, 0.f, 0.f, 0.f);                               \
        if (grow < M) av = *(const float4*)&(A)[(size_t)grow*(K) + k0 + a_col];    \
        float4 bv = *(const float4*)&(B)[(size_t)(k0 + b_row)*HD + colBase + b_col];\
        __syncthreads();                                                           \
        As[a_col+0][a_row] = av.x; As[a_col+1][a_row] = av.y;                      \
        As[a_col+2][a_row] = av.z; As[a_col+3][a_row] = av.w;                      \
        *(float4*)&Bs[b_row][b_col] = bv;                                          \
        __syncthreads();                                                           \
        _Pragma("unroll")                                                          \
        for (int kk = 0; kk < BK; ++kk) {                                          \
            float4 a = *(const float4*)&As[kk][ty << 2];                           \
            float4 b = *(const float4*)&Bs[kk][tx << 2];                           \
            acc[0]  += a.x*b.x; acc[1]  += a.x*b.y; acc[2]  += a.x*b.z; acc[3]  += a.x*b.w; \
            acc[4]  += a.y*b.x; acc[5]  += a.y*b.y; acc[6]  += a.y*b.z; acc[7]  += a.y*b.w; \
            acc[8]  += a.z*b.x; acc[9]  += a.z*b.y; acc[10] += a.z*b.z; acc[11] += a.z*b.w; \
            acc[12] += a.w*b.x; acc[13] += a.w*b.y; acc[14] += a.w*b.z; acc[15] += a.w*b.w; \
        }                                                                          \
    }

    GEMM_PHASE(A1, K1, B1, acc1)
    if (MODE != 0) { GEMM_PHASE(A2, K2, B2, acc2) }
#undef GEMM_PHASE

    #pragma unroll
    for (int i = 0; i < 4; ++i) {
        int row = rowBase + (ty << 2) + i;
        if (row >= M) continue;
        int n0 = colBase + (tx << 2);
        float4 v;
        float* vp = &v.x;
        #pragma unroll
        for (int j = 0; j < 4; ++j) {
            int n = n0 + j;
            float a1 = acc1[i*4+j], a2 = acc2[i*4+j];
            float val;
            if (MODE == 0) {
                val = a1 + (e0 ? e0[n] : 0.f);
            } else if (MODE == 1) {
                size_t off = (size_t)row*HD + n;
                float z  = sigm(e0[off] + a1);
                float p  = tanhf(e1[off] + a2);
                float sh = e2[off];
                val = (row == 0) ? 0.f : ((1.f - z)*sh + z*p);
            } else {
                float t = a1 + a2 + e0[n];
                val = fmaxf(t, 0.f) * e2[row];
            }
            vp[j] = val;
        }
        *(float4*)&C[(size_t)row*HD + n0] = v;
    }
}

// Per-message neighbor gather: sum_h = sum_j h[b[e,j]],
// sum_g = sum_j sigmoid(rx2[e] + hU[b[e,j]]) * h[b[e,j]]
__global__ void gather_msgs(const float* __restrict__ h, const float* __restrict__ hU,
                            const float* __restrict__ rx2, const int* __restrict__ bg,
                            float* __restrict__ sumh, float* __restrict__ sumg)
{
    __shared__ int s_nb[4][NBR];
    int e = blockIdx.x * 4 + threadIdx.y;             // NM divisible by 4
    if (threadIdx.x < NBR) s_nb[threadIdx.y][threadIdx.x] = bg[e*NBR + threadIdx.x];
    __syncthreads();
    int c = threadIdx.x << 2;                         // 64 threads cover 256 cols
    size_t base = (size_t)e*HD + c;
    float4 rxv = *(const float4*)&rx2[base];
    float4 sh = make_float4(0.f,0.f,0.f,0.f);
    float4 sg = make_float4(0.f,0.f,0.f,0.f);
    #pragma unroll
    for (int j = 0; j < NBR; ++j) {
        size_t nb = (size_t)s_nb[threadIdx.y][j]*HD + c;
        float4 hv = *(const float4*)&h[nb];
        float4 hu = *(const float4*)&hU[nb];
        sh.x += hv.x; sh.y += hv.y; sh.z += hv.z; sh.w += hv.w;
        sg.x += sigm(rxv.x + hu.x) * hv.x;
        sg.y += sigm(rxv.y + hu.y) * hv.y;
        sg.z += sigm(rxv.z + hu.z) * hv.z;
        sg.w += sigm(rxv.w + hu.w) * hv.w;
    }
    *(float4*)&sumh[base] = sh;
    *(float4*)&sumg[base] = sg;
}

// Per-node neighbor gather: nei[v] = sum_j h[a[v,j]]
__global__ void gather_nodes(const float* __restrict__ h, const int* __restrict__ ag,
                             float* __restrict__ nei)
{
    __shared__ int s_nb[4][NBR];
    int v = blockIdx.x * 4 + threadIdx.y;             // NN divisible by 4
    if (threadIdx.x < NBR) s_nb[threadIdx.y][threadIdx.x] = ag[v*NBR + threadIdx.x];
    __syncthreads();
    int c = threadIdx.x << 2;
    float4 s = make_float4(0.f,0.f,0.f,0.f);
    #pragma unroll
    for (int j = 0; j < NBR; ++j) {
        size_t nb = (size_t)s_nb[threadIdx.y][j]*HD + c;
        float4 hv = *(const float4*)&h[nb];
        s.x += hv.x; s.y += hv.y; s.z += hv.z; s.w += hv.w;
    }
    *(float4*)&nei[(size_t)v*HD + c] = s;
}

__global__ void zero_kernel(float4* p, size_t n4)
{
    size_t i = blockIdx.x*(size_t)blockDim.x + threadIdx.x;
    if (i < n4) p[i] = make_float4(0.f,0.f,0.f,0.f);
}

extern "C" void kernel_launch(void* const* d_in, const int* in_sizes, int n_in,
                              void* d_out, int out_size)
{
    const float* fnode  = (const float*)d_in[0];
    const float* fmess  = (const float*)d_in[1];
    const int*   agraph = (const int*)  d_in[2];
    const int*   bgraph = (const int*)  d_in[3];
    const float* mask   = (const float*)d_in[4];
    const float* W_z    = (const float*)d_in[5];
    const float* b_z    = (const float*)d_in[6];
    const float* W_r    = (const float*)d_in[7];
    const float* U_r    = (const float*)d_in[8];
    const float* b_ur   = (const float*)d_in[9];
    const float* W_h    = (const float*)d_in[10];
    const float* b_h    = (const float*)d_in[11];
    const float* W_o    = (const float*)d_in[12];
    const float* b_o    = (const float*)d_in[13];

    float* out_node = (float*)d_out;                  // [NN, HD]
    float* out_h    = out_node + (size_t)NN*HD;       // [NM, HD]

    float *rx2, *fz, *fh, *hU, *sumh, *sumg, *hA, *nei;
    cudaGetSymbolAddress((void**)&rx2,  g_rx2);
    cudaGetSymbolAddress((void**)&fz,   g_fz);
    cudaGetSymbolAddress((void**)&fh,   g_fh);
    cudaGetSymbolAddress((void**)&hU,   g_hU);
    cudaGetSymbolAddress((void**)&sumh, g_sumh);
    cudaGetSymbolAddress((void**)&sumg, g_sumg);
    cudaGetSymbolAddress((void**)&hA,   g_hA);
    cudaGetSymbolAddress((void**)&nei,  g_nei);

    const float* Wz_bot = W_z + (size_t)IND*HD;
    const float* Wh_bot = W_h + (size_t)IND*HD;
    const float* Wo_bot = W_o + (size_t)IND*HD;

    dim3 blk(256);
    dim3 gE(HD/BN, (NM + BM - 1)/BM);                 // (4, 1250)
    dim3 gV(HD/BN, (NN + BM - 1)/BM);                 // (4, 547)

    // Loop-invariant precompute (biases folded in):
    // fz = fmess@Wz_top + b_z ; fh = fmess@Wh_top + b_h ; rx2 = fmess@W_r + b_ur
    dual_gemm<0><<<gE, blk>>>(fmess, IND, W_z, nullptr, 0, nullptr, NM, b_z,  nullptr, nullptr, fz);
    dual_gemm<0><<<gE, blk>>>(fmess, IND, W_h, nullptr, 0, nullptr, NM, b_h,  nullptr, nullptr, fh);
    dual_gemm<0><<<gE, blk>>>(fmess, IND, W_r, nullptr, 0, nullptr, NM, b_ur, nullptr, nullptr, rx2);

    // h starts at zero
    {
        size_t n4 = (size_t)NM*HD/4;
        zero_kernel<<<(unsigned)((n4 + 255)/256), 256>>>((float4*)hA, n4);
    }

    // DEPTH=5 ping-pong: hA -> out_h -> hA -> ... -> out_h (final lands in d_out)
    float* hc = hA;
    float* hn = out_h;
    for (int d = 0; d < DEPTH; ++d) {
        // hU = h @ U_r   (replaces the [E,6,256]@[256,256] per-neighbor GEMM)
        dual_gemm<0><<<gE, blk>>>(hc, HD, U_r, nullptr, 0, nullptr, NM,
                                  nullptr, nullptr, nullptr, hU);
        gather_msgs<<<NM/4, dim3(64,4)>>>(hc, hU, rx2, bgraph, sumh, sumg);
        // z = sig(fz + sumh@Wz_bot); p = tanh(fh + sumg@Wh_bot);
        // h_new = ((1-z)*sumh + z*p) * (row != 0)
        dual_gemm<1><<<gE, blk>>>(sumh, HD, Wz_bot, sumg, HD, Wh_bot, NM,
                                  fz, fh, sumh, hn);
        float* t = hc; hc = hn; hn = t;
    }

    // Output layer: nei = sum_j h[agraph]; out = relu(fnode@Wo_top + nei@Wo_bot + b_o) * mask
    gather_nodes<<<NN/4, dim3(64,4)>>>(hc, agraph, nei);
    dual_gemm<2><<<gV, blk>>>(fnode, IND, W_o, nei, HD, Wo_bot, NN,
                              b_o, nullptr, mask, out_node);
}

// round 2
// speedup vs baseline: 1.1298x; 1.1298x over previous
#include <cuda_runtime.h>
#include <math.h>

#define NN 35000
#define NM 80000
#define NBR 6
#define IND 128
#define HD 256
#define DEPTH 5

#define BM 128
#define BN 128
#define BK 16

typedef unsigned long long ull;

// Scratch (allocation-free rule: __device__ globals)
__device__ float g_rx2 [(size_t)NM*HD];
__device__ float g_fz  [(size_t)NM*HD];
__device__ float g_fh  [(size_t)NM*HD];
__device__ float g_hU  [(size_t)NM*HD];
__device__ float g_sumh[(size_t)NM*HD];
__device__ float g_sumg[(size_t)NM*HD];
__device__ float g_hA  [(size_t)NM*HD];
__device__ float g_nei [(size_t)NN*HD];

__device__ __forceinline__ float sigm(float x){ return 1.0f/(1.0f+expf(-x)); }

__device__ __forceinline__ ull dup2(float a){
    ull r; asm("mov.b64 %0, {%1, %1};" : "=l"(r) : "f"(a)); return r;
}
__device__ __forceinline__ void fma2(ull& d, ull a, ull b){
    asm("fma.rn.f32x2 %0, %1, %2, %0;" : "+l"(d) : "l"(a), "l"(b));
}
__device__ __forceinline__ float2 unpk(ull v){
    float2 f; asm("mov.b64 {%0, %1}, %2;" : "=f"(f.x), "=f"(f.y) : "l"(v)); return f;
}

union F4U { float4 f; ull u[2]; };

// Dual-GEMM via packed fp32x2 FMA. 128x128x16 tiles, 8x8 thread tile.
// acc1 = A1[M,K1]@B1[K1,256], acc2 = A2[M,K2]@B2[K2,256]; B row-major ld=256.
// MODE 0: C = acc1 + bias(e0)
// MODE 1: GRU epilogue: z=sig(e0+acc1), p=tanh(e1+acc2), C=((1-z)*e2+z*p)*(row!=0)
// MODE 2: C = relu(acc1+acc2+e0[n]) * e2[row]
template<int MODE>
__global__ __launch_bounds__(256)
void dual_gemm(const float* __restrict__ A1, int K1, const float* __restrict__ B1,
               const float* __restrict__ A2, int K2, const float* __restrict__ B2,
               int M,
               const float* __restrict__ e0, const float* __restrict__ e1,
               const float* __restrict__ e2, float* __restrict__ C)
{
    __shared__ float As[BK][BM];
    __shared__ float Bs[BK][BN];
    const int tid = threadIdx.x;
    const int tx = tid & 15;            // col group (8 cols)
    const int ty = tid >> 4;            // row group (8 rows)
    const int rowBase = blockIdx.y * BM;
    const int colBase = blockIdx.x * BN;
    // A tile load: 128 rows x 16 cols; conflict-free STS (bank = row%32)
    const int ar = tid & 127;
    const int ac = (tid >> 7) << 3;
    // B tile load: 16 rows x 128 cols
    const int br = tid >> 4;
    const int bc = (tid & 15) << 3;
    const int grow = rowBase + ar;

    ull acc1[8][4], acc2[8][4];
    #pragma unroll
    for (int i = 0; i < 8; ++i)
        #pragma unroll
        for (int j = 0; j < 4; ++j) { acc1[i][j] = 0ull; acc2[i][j] = 0ull; }

#define GEMM_PHASE(A, K, B, acc)                                                    \
    for (int k0 = 0; k0 < (K); k0 += BK) {                                          \
        float4 av0 = make_float4(0.f,0.f,0.f,0.f), av1 = av0;                       \
        if (grow < M) {                                                             \
            av0 = *(const float4*)&(A)[(size_t)grow*(K) + k0 + ac];                 \
            av1 = *(const float4*)&(A)[(size_t)grow*(K) + k0 + ac + 4];             \
        }                                                                           \
        float4 bv0 = *(const float4*)&(B)[(size_t)(k0+br)*HD + colBase + bc];       \
        float4 bv1 = *(const float4*)&(B)[(size_t)(k0+br)*HD + colBase + bc + 4];   \
        __syncthreads();                                                            \
        As[ac+0][ar]=av0.x; As[ac+1][ar]=av0.y; As[ac+2][ar]=av0.z; As[ac+3][ar]=av0.w; \
        As[ac+4][ar]=av1.x; As[ac+5][ar]=av1.y; As[ac+6][ar]=av1.z; As[ac+7][ar]=av1.w; \
        *(float4*)&Bs[br][bc]   = bv0;                                              \
        *(float4*)&Bs[br][bc+4] = bv1;                                              \
        __syncthreads();                                                            \
        _Pragma("unroll")                                                           \
        for (int kk = 0; kk < BK; ++kk) {                                           \
            F4U a0, a1, b0, b1;                                                     \
            a0.f = *(const float4*)&As[kk][ty << 3];                                \
            a1.f = *(const float4*)&As[kk][(ty << 3) + 4];                          \
            b0.f = *(const float4*)&Bs[kk][tx << 3];                                \
            b1.f = *(const float4*)&Bs[kk][(tx << 3) + 4];                          \
            ull ap[8];                                                              \
            ap[0]=dup2(a0.f.x); ap[1]=dup2(a0.f.y); ap[2]=dup2(a0.f.z); ap[3]=dup2(a0.f.w); \
            ap[4]=dup2(a1.f.x); ap[5]=dup2(a1.f.y); ap[6]=dup2(a1.f.z); ap[7]=dup2(a1.f.w); \
            ull bp[4] = { b0.u[0], b0.u[1], b1.u[0], b1.u[1] };                     \
            _Pragma("unroll")                                                       \
            for (int i = 0; i < 8; ++i) {                                           \
                fma2(acc[i][0], ap[i], bp[0]);                                      \
                fma2(acc[i][1], ap[i], bp[1]);                                      \
                fma2(acc[i][2], ap[i], bp[2]);                                      \
                fma2(acc[i][3], ap[i], bp[3]);                                      \
            }                                                                       \
        }                                                                           \
    }

    GEMM_PHASE(A1, K1, B1, acc1)
    if (MODE != 0) { GEMM_PHASE(A2, K2, B2, acc2) }
#undef GEMM_PHASE

    const int n0 = colBase + (tx << 3);
    #pragma unroll
    for (int i = 0; i < 8; ++i) {
        int row = rowBase + (ty << 3) + i;
        if (row >= M) continue;
        float v1[8], v2[8];
        #pragma unroll
        for (int j = 0; j < 4; ++j) {
            float2 p = unpk(acc1[i][j]); v1[2*j] = p.x; v1[2*j+1] = p.y;
            if (MODE != 0) { float2 q = unpk(acc2[i][j]); v2[2*j] = q.x; v2[2*j+1] = q.y; }
        }
        float out[8];
        if (MODE == 0) {
            #pragma unroll
            for (int j = 0; j < 8; ++j) out[j] = v1[j] + (e0 ? e0[n0+j] : 0.f);
        } else if (MODE == 1) {
            size_t off = (size_t)row*HD + n0;
            float4 z0 = *(const float4*)&e0[off], z1 = *(const float4*)&e0[off+4];
            float4 h0 = *(const float4*)&e1[off], h1 = *(const float4*)&e1[off+4];
            float4 s0 = *(const float4*)&e2[off], s1 = *(const float4*)&e2[off+4];
            const float* zp = &z0.x; const float* hp = &h0.x; const float* sp = &s0.x;
            float zb[8] = {z0.x,z0.y,z0.z,z0.w,z1.x,z1.y,z1.z,z1.w};
            float hb[8] = {h0.x,h0.y,h0.z,h0.w,h1.x,h1.y,h1.z,h1.w};
            float sb[8] = {s0.x,s0.y,s0.z,s0.w,s1.x,s1.y,s1.z,s1.w};
            (void)zp; (void)hp; (void)sp;
            #pragma unroll
            for (int j = 0; j < 8; ++j) {
                float z = sigm(zb[j] + v1[j]);
                float p = tanhf(hb[j] + v2[j]);
                out[j] = (row == 0) ? 0.f : ((1.f - z)*sb[j] + z*p);
            }
        } else {
            float m = e2[row];
            #pragma unroll
            for (int j = 0; j < 8; ++j) {
                float t = v1[j] + v2[j] + e0[n0+j];
                out[j] = fmaxf(t, 0.f) * m;
            }
        }
        float4 o0 = make_float4(out[0],out[1],out[2],out[3]);
        float4 o1 = make_float4(out[4],out[5],out[6],out[7]);
        *(float4*)&C[(size_t)row*HD + n0]     = o0;
        *(float4*)&C[(size_t)row*HD + n0 + 4] = o1;
    }
}

// Step 1 degenerates (h=0): h1 = sigmoid(fz) * tanh(fh), row 0 masked to 0.
__global__ void first_step(const float4* __restrict__ fz, const float4* __restrict__ fh,
                           float4* __restrict__ h1)
{
    size_t i = blockIdx.x*(size_t)blockDim.x + threadIdx.x;   // NM*HD/4 elements
    float4 z = fz[i], h = fh[i];
    float4 o;
    o.x = sigm(z.x)*tanhf(h.x);
    o.y = sigm(z.y)*tanhf(h.y);
    o.z = sigm(z.z)*tanhf(h.z);
    o.w = sigm(z.w)*tanhf(h.w);
    if (i < HD/4) o = make_float4(0.f,0.f,0.f,0.f);   // message 0 is null
    h1[i] = o;
}

// Per-message neighbor gather: sum_h = sum_j h[b[e,j]],
// sum_g = sum_j sigmoid(rx2[e] + hU[b[e,j]]) * h[b[e,j]]
__global__ void gather_msgs(const float* __restrict__ h, const float* __restrict__ hU,
                            const float* __restrict__ rx2, const int* __restrict__ bg,
                            float* __restrict__ sumh, float* __restrict__ sumg)
{
    __shared__ int s_nb[4][NBR];
    int e = blockIdx.x * 4 + threadIdx.y;             // NM divisible by 4
    if (threadIdx.x < NBR) s_nb[threadIdx.y][threadIdx.x] = bg[e*NBR + threadIdx.x];
    __syncthreads();
    int c = threadIdx.x << 2;                         // 64 threads cover 256 cols
    size_t base = (size_t)e*HD + c;
    float4 rxv = *(const float4*)&rx2[base];
    float4 sh = make_float4(0.f,0.f,0.f,0.f);
    float4 sg = make_float4(0.f,0.f,0.f,0.f);
    #pragma unroll
    for (int j = 0; j < NBR; ++j) {
        size_t nb = (size_t)s_nb[threadIdx.y][j]*HD + c;
        float4 hv = *(const float4*)&h[nb];
        float4 hu = *(const float4*)&hU[nb];
        sh.x += hv.x; sh.y += hv.y; sh.z += hv.z; sh.w += hv.w;
        sg.x += sigm(rxv.x + hu.x) * hv.x;
        sg.y += sigm(rxv.y + hu.y) * hv.y;
        sg.z += sigm(rxv.z + hu.z) * hv.z;
        sg.w += sigm(rxv.w + hu.w) * hv.w;
    }
    *(float4*)&sumh[base] = sh;
    *(float4*)&sumg[base] = sg;
}

// Per-node neighbor gather: nei[v] = sum_j h[a[v,j]]
__global__ void gather_nodes(const float* __restrict__ h, const int* __restrict__ ag,
                             float* __restrict__ nei)
{
    __shared__ int s_nb[4][NBR];
    int v = blockIdx.x * 4 + threadIdx.y;             // NN divisible by 4
    if (threadIdx.x < NBR) s_nb[threadIdx.y][threadIdx.x] = ag[v*NBR + threadIdx.x];
    __syncthreads();
    int c = threadIdx.x << 2;
    float4 s = make_float4(0.f,0.f,0.f,0.f);
    #pragma unroll
    for (int j = 0; j < NBR; ++j) {
        size_t nb = (size_t)s_nb[threadIdx.y][j]*HD + c;
        float4 hv = *(const float4*)&h[nb];
        s.x += hv.x; s.y += hv.y; s.z += hv.z; s.w += hv.w;
    }
    *(float4*)&nei[(size_t)v*HD + c] = s;
}

extern "C" void kernel_launch(void* const* d_in, const int* in_sizes, int n_in,
                              void* d_out, int out_size)
{
    const float* fnode  = (const float*)d_in[0];
    const float* fmess  = (const float*)d_in[1];
    const int*   agraph = (const int*)  d_in[2];
    const int*   bgraph = (const int*)  d_in[3];
    const float* mask   = (const float*)d_in[4];
    const float* W_z    = (const float*)d_in[5];
    const float* b_z    = (const float*)d_in[6];
    const float* W_r    = (const float*)d_in[7];
    const float* U_r    = (const float*)d_in[8];
    const float* b_ur   = (const float*)d_in[9];
    const float* W_h    = (const float*)d_in[10];
    const float* b_h    = (const float*)d_in[11];
    const float* W_o    = (const float*)d_in[12];
    const float* b_o    = (const float*)d_in[13];

    float* out_node = (float*)d_out;                  // [NN, HD]
    float* out_h    = out_node + (size_t)NN*HD;       // [NM, HD]

    float *rx2, *fz, *fh, *hU, *sumh, *sumg, *hA, *nei;
    cudaGetSymbolAddress((void**)&rx2,  g_rx2);
    cudaGetSymbolAddress((void**)&fz,   g_fz);
    cudaGetSymbolAddress((void**)&fh,   g_fh);
    cudaGetSymbolAddress((void**)&hU,   g_hU);
    cudaGetSymbolAddress((void**)&sumh, g_sumh);
    cudaGetSymbolAddress((void**)&sumg, g_sumg);
    cudaGetSymbolAddress((void**)&hA,   g_hA);
    cudaGetSymbolAddress((void**)&nei,  g_nei);

    const float* Wz_bot = W_z + (size_t)IND*HD;
    const float* Wh_bot = W_h + (size_t)IND*HD;
    const float* Wo_bot = W_o + (size_t)IND*HD;

    dim3 blk(256);
    dim3 gE(HD/BN, NM/BM);                            // (2, 625)
    dim3 gV(HD/BN, (NN + BM - 1)/BM);                 // (2, 274)

    // Loop-invariant precompute (biases folded in)
    dual_gemm<0><<<gE, blk>>>(fmess, IND, W_z, nullptr, 0, nullptr, NM, b_z,  nullptr, nullptr, fz);
    dual_gemm<0><<<gE, blk>>>(fmess, IND, W_h, nullptr, 0, nullptr, NM, b_h,  nullptr, nullptr, fh);
    dual_gemm<0><<<gE, blk>>>(fmess, IND, W_r, nullptr, 0, nullptr, NM, b_ur, nullptr, nullptr, rx2);

    // Step 1 is elementwise (h starts at 0): h1 = sig(fz)*tanh(fh), row0 = 0.
    // Write into out_h so the 4 remaining steps' ping-pong ends in out_h.
    first_step<<<(NM*HD/4)/256, 256>>>((const float4*)fz, (const float4*)fh, (float4*)out_h);

    float* hc = out_h;
    float* hn = hA;
    for (int d = 1; d < DEPTH; ++d) {
        dual_gemm<0><<<gE, blk>>>(hc, HD, U_r, nullptr, 0, nullptr, NM,
                                  nullptr, nullptr, nullptr, hU);
        gather_msgs<<<NM/4, dim3(64,4)>>>(hc, hU, rx2, bgraph, sumh, sumg);
        dual_gemm<1><<<gE, blk>>>(sumh, HD, Wz_bot, sumg, HD, Wh_bot, NM,
                                  fz, fh, sumh, hn);
        float* t = hc; hc = hn; hn = t;
    }

    // Output layer
    gather_nodes<<<NN/4, dim3(64,4)>>>(hc, agraph, nei);
    dual_gemm<2><<<gV, blk>>>(fnode, IND, W_o, nei, HD, Wo_bot, NN,
                              b_o, nullptr, mask, out_node);
}

// round 4
// speedup vs baseline: 1.9727x; 1.7460x over previous
#include <cuda_runtime.h>
#include <cuda_bf16.h>
#include <math.h>
#include <cstdint>

#define NN 35000
#define NM 80000
#define NBR 6
#define IND 128
#define HD 256
#define DEPTH 5

// ---------------- scratch (__device__ globals; no allocs) ----------------
__device__ float g_rx2 [(size_t)NM*HD];
__device__ float g_fz  [(size_t)NM*HD];
__device__ float g_fh  [(size_t)NM*HD];
__device__ float g_hU  [(size_t)NM*HD];
__device__ float g_sumh[(size_t)NM*HD];
__device__ float g_sumg[(size_t)NM*HD];
__device__ float g_hA  [(size_t)NM*HD];
__device__ float g_nei [(size_t)NN*HD];

// transposed+split weights: [N=256, K] bf16, hi and lo planes
#define OFF_WZT 0
#define OFF_WHT 32768
#define OFF_WR  65536
#define OFF_WOT 98304
#define OFF_UR  131072
#define OFF_WZB 196608
#define OFF_WHB 262144
#define OFF_WOB 327680
__device__ __nv_bfloat16 g_bh[393216];
__device__ __nv_bfloat16 g_bl[393216];

__device__ __forceinline__ float sigm(float x){ return 1.0f/(1.0f+expf(-x)); }

// ---------------- mma / ldmatrix helpers (compute_103-safe, sm_80+) ------
__device__ __forceinline__ uint32_t smem_addr(const void* p){
    return (uint32_t)__cvta_generic_to_shared(p);
}
__device__ __forceinline__ void ldsm4(uint32_t a, uint32_t& r0, uint32_t& r1,
                                      uint32_t& r2, uint32_t& r3){
    asm volatile("ldmatrix.sync.aligned.m8n8.x4.shared.b16 {%0,%1,%2,%3}, [%4];"
                 : "=r"(r0), "=r"(r1), "=r"(r2), "=r"(r3) : "r"(a));
}
__device__ __forceinline__ void mma16816(float* c, const uint32_t* a, const uint32_t* b){
    asm volatile(
        "mma.sync.aligned.m16n8k16.row.col.f32.bf16.bf16.f32 "
        "{%0,%1,%2,%3}, {%4,%5,%6,%7}, {%8,%9}, {%0,%1,%2,%3};"
        : "+f"(c[0]), "+f"(c[1]), "+f"(c[2]), "+f"(c[3])
        : "r"(a[0]), "r"(a[1]), "r"(a[2]), "r"(a[3]), "r"(b[0]), "r"(b[1]));
}

__device__ __forceinline__ void cvt_split8(float4 v0, float4 v1, uint4& hi, uint4& lo){
    float f[8] = {v0.x,v0.y,v0.z,v0.w,v1.x,v1.y,v1.z,v1.w};
    uint32_t hh[8], ll[8];
    #pragma unroll
    for (int j = 0; j < 8; ++j) {
        __nv_bfloat16 h = __float2bfloat16_rn(f[j]);
        float hf = __bfloat162float(h);
        __nv_bfloat16 l = __float2bfloat16_rn(f[j] - hf);
        hh[j] = (uint32_t)__bfloat16_as_ushort(h);
        ll[j] = (uint32_t)__bfloat16_as_ushort(l);
    }
    hi = make_uint4(hh[0]|(hh[1]<<16), hh[2]|(hh[3]<<16), hh[4]|(hh[5]<<16), hh[6]|(hh[7]<<16));
    lo = make_uint4(ll[0]|(ll[1]<<16), ll[2]|(ll[3]<<16), ll[4]|(ll[5]<<16), ll[6]|(ll[7]<<16));
}

// smem layout (bytes): A_hi/A_lo/B_hi/B_lo planes of 128 rows x 40 bf16 (pad)
#define PADK 40
#define SM_AH 0
#define SM_AL 10240
#define SM_BH 20480
#define SM_BL 30720
#define SM_Z  40960
#define ZSTRIDE 130
#define SMEM_SMALL 40960
#define SMEM_BIG   (40960 + 128*ZSTRIDE*4)

// One phase: acc += split(A[rowBase:+128, :K]) @ B^T, B = [256,K] bf16 hi/lo planes,
// taking B rows [colBase, colBase+128).
__device__ __forceinline__ void run_phase(
    const float* __restrict__ A, int K,
    const __nv_bfloat16* __restrict__ Bh, const __nv_bfloat16* __restrict__ Bl,
    float acc[2][4][4], char* sm, int tid, int rowBase, int colBase, int M)
{
    const int lane = tid & 31, wid = tid >> 5;
    const int wm = wid >> 2, wn = wid & 3;
    const int row = tid >> 2, ks = (tid & 3) << 3;     // tile fill: 128 rows x 32 cols
    const int grow = rowBase + row;
    const int g = lane >> 3, r = lane & 7;

    const uint32_t aAH = smem_addr(sm + SM_AH);
    const uint32_t aAL = smem_addr(sm + SM_AL);
    const uint32_t aBH = smem_addr(sm + SM_BH);
    const uint32_t aBL = smem_addr(sm + SM_BL);

    const int nchunks = K >> 5;
    for (int c = 0; c < nchunks; ++c) {
        // load A chunk (fp32 -> bf16 hi/lo) and B chunk (bf16 planes)
        float4 v0 = make_float4(0.f,0.f,0.f,0.f), v1 = v0;
        if (grow < M) {
            const float* p = A + (size_t)grow*K + (c << 5) + ks;
            v0 = *(const float4*)p; v1 = *(const float4*)(p + 4);
        }
        uint4 ahi, alo; cvt_split8(v0, v1, ahi, alo);
        size_t boff = (size_t)(colBase + row)*K + (c << 5) + ks;
        uint4 wh = *(const uint4*)(Bh + boff);
        uint4 wl = *(const uint4*)(Bl + boff);

        __syncthreads();                                // prior ldmatrix done
        uint32_t so = (uint32_t)(row*PADK + ks) * 2;
        *(uint4*)(sm + SM_AH + so) = ahi;
        *(uint4*)(sm + SM_AL + so) = alo;
        *(uint4*)(sm + SM_BH + so) = wh;
        *(uint4*)(sm + SM_BL + so) = wl;
        __syncthreads();

        #pragma unroll
        for (int ki = 0; ki < 2; ++ki) {
            // A fragments: 2 m16 blocks x (hi, lo)
            uint32_t ah[2][4], al[2][4];
            {
                int arow = wm*32 + (g & 1)*8 + r;
                int acol = ki*16 + (g >> 1)*8;
                uint32_t off = (uint32_t)(arow*PADK + acol) * 2;
                ldsm4(aAH + off,               ah[0][0], ah[0][1], ah[0][2], ah[0][3]);
                ldsm4(aAH + off + 16*PADK*2,   ah[1][0], ah[1][1], ah[1][2], ah[1][3]);
                ldsm4(aAL + off,               al[0][0], al[0][1], al[0][2], al[0][3]);
                ldsm4(aAL + off + 16*PADK*2,   al[1][0], al[1][1], al[1][2], al[1][3]);
            }
            // B fragments: 4 n8 blocks x (hi, lo)
            uint32_t bhf[4][2], blf[4][2];
            {
                int nrow = wn*32 + (g >> 1)*8 + r;
                int ncol = ki*16 + (g & 1)*8;
                uint32_t off = (uint32_t)(nrow*PADK + ncol) * 2;
                ldsm4(aBH + off,             bhf[0][0], bhf[0][1], bhf[1][0], bhf[1][1]);
                ldsm4(aBH + off + 16*PADK*2, bhf[2][0], bhf[2][1], bhf[3][0], bhf[3][1]);
                ldsm4(aBL + off,             blf[0][0], blf[0][1], blf[1][0], blf[1][1]);
                ldsm4(aBL + off + 16*PADK*2, blf[2][0], blf[2][1], blf[3][0], blf[3][1]);
            }
            #pragma unroll
            for (int mi = 0; mi < 2; ++mi)
                #pragma unroll
                for (int ni = 0; ni < 4; ++ni) {
                    mma16816(acc[mi][ni], ah[mi], bhf[ni]);   // hi*hi
                    mma16816(acc[mi][ni], ah[mi], blf[ni]);   // hi*lo
                    mma16816(acc[mi][ni], al[mi], bhf[ni]);   // lo*hi
                }
        }
    }
}

// MODE 0: C = D1 + (e0 ? e0[col] : 0)
// MODE 1: D1 = A1@B1, D2 = A2@B2; z=sig(e0+D1), p=tanh(e1+D2);
//         C = ((1-z)*e2 + z*p), row 0 forced to 0
// MODE 2: D = A1@B1 + A2@B2; C = relu(D + e0[col]) * e2[row]
template<int MODE>
__global__ __launch_bounds__(512, 1)
void mma_gemm(const float* __restrict__ A1, int K1,
              const __nv_bfloat16* __restrict__ B1h, const __nv_bfloat16* __restrict__ B1l,
              const float* __restrict__ A2, int K2,
              const __nv_bfloat16* __restrict__ B2h, const __nv_bfloat16* __restrict__ B2l,
              int M,
              const float* __restrict__ e0, const float* __restrict__ e1,
              const float* __restrict__ e2, float* __restrict__ C)
{
    extern __shared__ char sm[];
    const int tid = threadIdx.x;
    const int colBase = (blockIdx.x & 1) << 7;
    const int rowBase = (int)(blockIdx.x >> 1) << 7;
    const int lane = tid & 31, wid = tid >> 5;
    const int wm = wid >> 2, wn = wid & 3;
    const int tq = lane >> 2, tr = lane & 3;

    float acc[2][4][4];
    #pragma unroll
    for (int i = 0; i < 2; ++i)
        #pragma unroll
        for (int j = 0; j < 4; ++j)
            #pragma unroll
            for (int q = 0; q < 4; ++q) acc[i][j][q] = 0.f;

    run_phase(A1, K1, B1h, B1l, acc, sm, tid, rowBase, colBase, M);

    if (MODE == 0) {
        #pragma unroll
        for (int mi = 0; mi < 2; ++mi)
            #pragma unroll
            for (int ni = 0; ni < 4; ++ni) {
                int gcol = colBase + wn*32 + ni*8 + tr*2;
                int r0 = rowBase + wm*32 + mi*16 + tq;
                float bx = 0.f, by = 0.f;
                if (e0) { float2 b = *(const float2*)&e0[gcol]; bx = b.x; by = b.y; }
                float2 o0 = make_float2(acc[mi][ni][0] + bx, acc[mi][ni][1] + by);
                float2 o1 = make_float2(acc[mi][ni][2] + bx, acc[mi][ni][3] + by);
                *(float2*)&C[(size_t)r0*HD + gcol]     = o0;
                *(float2*)&C[(size_t)(r0+8)*HD + gcol] = o1;
            }
    } else if (MODE == 1) {
        // stash z in smem (same-thread readback; no sync needed)
        float* zbuf = (float*)(sm + SM_Z);
        #pragma unroll
        for (int mi = 0; mi < 2; ++mi)
            #pragma unroll
            for (int ni = 0; ni < 4; ++ni) {
                int lrow = wm*32 + mi*16 + tq;
                int lcol = wn*32 + ni*8 + tr*2;
                int r0 = rowBase + lrow;
                float2 ea = *(const float2*)&e0[(size_t)r0*HD + colBase + lcol];
                float2 eb = *(const float2*)&e0[(size_t)(r0+8)*HD + colBase + lcol];
                zbuf[lrow*ZSTRIDE + lcol]       = sigm(ea.x + acc[mi][ni][0]);
                zbuf[lrow*ZSTRIDE + lcol + 1]   = sigm(ea.y + acc[mi][ni][1]);
                zbuf[(lrow+8)*ZSTRIDE + lcol]   = sigm(eb.x + acc[mi][ni][2]);
                zbuf[(lrow+8)*ZSTRIDE + lcol+1] = sigm(eb.y + acc[mi][ni][3]);
            }
        #pragma unroll
        for (int i = 0; i < 2; ++i)
            #pragma unroll
            for (int j = 0; j < 4; ++j)
                #pragma unroll
                for (int q = 0; q < 4; ++q) acc[i][j][q] = 0.f;

        run_phase(A2, K2, B2h, B2l, acc, sm, tid, rowBase, colBase, M);

        #pragma unroll
        for (int mi = 0; mi < 2; ++mi)
            #pragma unroll
            for (int ni = 0; ni < 4; ++ni) {
                int lrow = wm*32 + mi*16 + tq;
                int lcol = wn*32 + ni*8 + tr*2;
                int r0 = rowBase + lrow;
                size_t o0 = (size_t)r0*HD + colBase + lcol;
                size_t o1 = (size_t)(r0+8)*HD + colBase + lcol;
                float2 ha = *(const float2*)&e1[o0];
                float2 hb = *(const float2*)&e1[o1];
                float2 sa = *(const float2*)&e2[o0];
                float2 sb = *(const float2*)&e2[o1];
                float z0 = zbuf[lrow*ZSTRIDE + lcol];
                float z1 = zbuf[lrow*ZSTRIDE + lcol + 1];
                float z2 = zbuf[(lrow+8)*ZSTRIDE + lcol];
                float z3 = zbuf[(lrow+8)*ZSTRIDE + lcol + 1];
                float p0 = tanhf(ha.x + acc[mi][ni][0]);
                float p1 = tanhf(ha.y + acc[mi][ni][1]);
                float p2 = tanhf(hb.x + acc[mi][ni][2]);
                float p3 = tanhf(hb.y + acc[mi][ni][3]);
                float2 u0 = make_float2((1.f - z0)*sa.x + z0*p0, (1.f - z1)*sa.y + z1*p1);
                float2 u1 = make_float2((1.f - z2)*sb.x + z2*p2, (1.f - z3)*sb.y + z3*p3);
                if (r0 == 0) u0 = make_float2(0.f, 0.f);   // null message row
                *(float2*)&C[o0] = u0;
                *(float2*)&C[o1] = u1;
            }
    } else {
        run_phase(A2, K2, B2h, B2l, acc, sm, tid, rowBase, colBase, M);
        #pragma unroll
        for (int mi = 0; mi < 2; ++mi)
            #pragma unroll
            for (int ni = 0; ni < 4; ++ni) {
                int gcol = colBase + wn*32 + ni*8 + tr*2;
                int r0 = rowBase + wm*32 + mi*16 + tq;
                float2 b = *(const float2*)&e0[gcol];
                if (r0 < M) {
                    float m = e2[r0];
                    float2 o = make_float2(fmaxf(acc[mi][ni][0] + b.x, 0.f) * m,
                                           fmaxf(acc[mi][ni][1] + b.y, 0.f) * m);
                    *(float2*)&C[(size_t)r0*HD + gcol] = o;
                }
                if (r0 + 8 < M) {
                    float m = e2[r0+8];
                    float2 o = make_float2(fmaxf(acc[mi][ni][2] + b.x, 0.f) * m,
                                           fmaxf(acc[mi][ni][3] + b.y, 0.f) * m);
                    *(float2*)&C[(size_t)(r0+8)*HD + gcol] = o;
                }
            }
    }
}

// transpose + bf16 hi/lo split of W[K,256] -> out[N=256, K]
__global__ void prep_w(const float* __restrict__ W, __nv_bfloat16* __restrict__ oh,
                       __nv_bfloat16* __restrict__ ol, int K, int kshift)
{
    int i = blockIdx.x * blockDim.x + threadIdx.x;
    int k = i & (K - 1);
    int n = i >> kshift;
    float x = W[(size_t)k * HD + n];
    __nv_bfloat16 h = __float2bfloat16_rn(x);
    __nv_bfloat16 lo = __float2bfloat16_rn(x - __bfloat162float(h));
    oh[i] = h; ol[i] = lo;
}

// Step 1 degenerates (h=0): h1 = sigmoid(fz) * tanh(fh), row 0 masked.
__global__ void first_step(const float4* __restrict__ fz, const float4* __restrict__ fh,
                           float4* __restrict__ h1)
{
    size_t i = blockIdx.x*(size_t)blockDim.x + threadIdx.x;
    float4 z = fz[i], h = fh[i];
    float4 o;
    o.x = sigm(z.x)*tanhf(h.x);
    o.y = sigm(z.y)*tanhf(h.y);
    o.z = sigm(z.z)*tanhf(h.z);
    o.w = sigm(z.w)*tanhf(h.w);
    if (i < HD/4) o = make_float4(0.f,0.f,0.f,0.f);
    h1[i] = o;
}

__global__ void gather_msgs(const float* __restrict__ h, const float* __restrict__ hU,
                            const float* __restrict__ rx2, const int* __restrict__ bg,
                            float* __restrict__ sumh, float* __restrict__ sumg)
{
    __shared__ int s_nb[4][NBR];
    int e = blockIdx.x * 4 + threadIdx.y;
    if (threadIdx.x < NBR) s_nb[threadIdx.y][threadIdx.x] = bg[e*NBR + threadIdx.x];
    __syncthreads();
    int c = threadIdx.x << 2;
    size_t base = (size_t)e*HD + c;
    float4 rxv = *(const float4*)&rx2[base];
    float4 sh = make_float4(0.f,0.f,0.f,0.f);
    float4 sg = make_float4(0.f,0.f,0.f,0.f);
    #pragma unroll
    for (int j = 0; j < NBR; ++j) {
        size_t nb = (size_t)s_nb[threadIdx.y][j]*HD + c;
        float4 hv = *(const float4*)&h[nb];
        float4 hu = *(const float4*)&hU[nb];
        sh.x += hv.x; sh.y += hv.y; sh.z += hv.z; sh.w += hv.w;
        sg.x += sigm(rxv.x + hu.x) * hv.x;
        sg.y += sigm(rxv.y + hu.y) * hv.y;
        sg.z += sigm(rxv.z + hu.z) * hv.z;
        sg.w += sigm(rxv.w + hu.w) * hv.w;
    }
    *(float4*)&sumh[base] = sh;
    *(float4*)&sumg[base] = sg;
}

__global__ void gather_nodes(const float* __restrict__ h, const int* __restrict__ ag,
                             float* __restrict__ nei)
{
    __shared__ int s_nb[4][NBR];
    int v = blockIdx.x * 4 + threadIdx.y;
    if (threadIdx.x < NBR) s_nb[threadIdx.y][threadIdx.x] = ag[v*NBR + threadIdx.x];
    __syncthreads();
    int c = threadIdx.x << 2;
    float4 s = make_float4(0.f,0.f,0.f,0.f);
    #pragma unroll
    for (int j = 0; j < NBR; ++j) {
        size_t nb = (size_t)s_nb[threadIdx.y][j]*HD + c;
        float4 hv = *(const float4*)&h[nb];
        s.x += hv.x; s.y += hv.y; s.z += hv.z; s.w += hv.w;
    }
    *(float4*)&nei[(size_t)v*HD + c] = s;
}

extern "C" void kernel_launch(void* const* d_in, const int* in_sizes, int n_in,
                              void* d_out, int out_size)
{
    const float* fnode  = (const float*)d_in[0];
    const float* fmess  = (const float*)d_in[1];
    const int*   agraph = (const int*)  d_in[2];
    const int*   bgraph = (const int*)  d_in[3];
    const float* mask   = (const float*)d_in[4];
    const float* W_z    = (const float*)d_in[5];
    const float* b_z    = (const float*)d_in[6];
    const float* W_r    = (const float*)d_in[7];
    const float* U_r    = (const float*)d_in[8];
    const float* b_ur   = (const float*)d_in[9];
    const float* W_h    = (const float*)d_in[10];
    const float* b_h    = (const float*)d_in[11];
    const float* W_o    = (const float*)d_in[12];
    const float* b_o    = (const float*)d_in[13];

    float* out_node = (float*)d_out;
    float* out_h    = out_node + (size_t)NN*HD;

    float *rx2, *fz, *fh, *hU, *sumh, *sumg, *hA, *nei;
    __nv_bfloat16 *bh, *bl;
    cudaGetSymbolAddress((void**)&rx2,  g_rx2);
    cudaGetSymbolAddress((void**)&fz,   g_fz);
    cudaGetSymbolAddress((void**)&fh,   g_fh);
    cudaGetSymbolAddress((void**)&hU,   g_hU);
    cudaGetSymbolAddress((void**)&sumh, g_sumh);
    cudaGetSymbolAddress((void**)&sumg, g_sumg);
    cudaGetSymbolAddress((void**)&hA,   g_hA);
    cudaGetSymbolAddress((void**)&nei,  g_nei);
    cudaGetSymbolAddress((void**)&bh,   g_bh);
    cudaGetSymbolAddress((void**)&bl,   g_bl);

    cudaFuncSetAttribute(mma_gemm<0>, cudaFuncAttributeMaxDynamicSharedMemorySize, SMEM_SMALL);
    cudaFuncSetAttribute(mma_gemm<1>, cudaFuncAttributeMaxDynamicSharedMemorySize, SMEM_BIG);
    cudaFuncSetAttribute(mma_gemm<2>, cudaFuncAttributeMaxDynamicSharedMemorySize, SMEM_SMALL);

    // ---- weight prep: transpose + hi/lo split ----
    prep_w<<<128, 256>>>(W_z,                  bh+OFF_WZT, bl+OFF_WZT, IND, 7);
    prep_w<<<128, 256>>>(W_h,                  bh+OFF_WHT, bl+OFF_WHT, IND, 7);
    prep_w<<<128, 256>>>(W_r,                  bh+OFF_WR,  bl+OFF_WR,  IND, 7);
    prep_w<<<128, 256>>>(W_o,                  bh+OFF_WOT, bl+OFF_WOT, IND, 7);
    prep_w<<<256, 256>>>(U_r,                  bh+OFF_UR,  bl+OFF_UR,  HD, 8);
    prep_w<<<256, 256>>>(W_z + (size_t)IND*HD, bh+OFF_WZB, bl+OFF_WZB, HD, 8);
    prep_w<<<256, 256>>>(W_h + (size_t)IND*HD, bh+OFF_WHB, bl+OFF_WHB, HD, 8);
    prep_w<<<256, 256>>>(W_o + (size_t)IND*HD, bh+OFF_WOB, bl+OFF_WOB, HD, 8);

    const int gE = (NM / 128) * 2;            // 1250 (row tiles x 2 col tiles)
    const int gV = ((NN + 127) / 128) * 2;    // 548

    // loop-invariant GEMMs (bias folded via epilogue)
    mma_gemm<0><<<gE, 512, SMEM_SMALL>>>(fmess, IND, bh+OFF_WZT, bl+OFF_WZT,
                                         nullptr, 0, nullptr, nullptr, NM,
                                         b_z, nullptr, nullptr, fz);
    mma_gemm<0><<<gE, 512, SMEM_SMALL>>>(fmess, IND, bh+OFF_WHT, bl+OFF_WHT,
                                         nullptr, 0, nullptr, nullptr, NM,
                                         b_h, nullptr, nullptr, fh);
    mma_gemm<0><<<gE, 512, SMEM_SMALL>>>(fmess, IND, bh+OFF_WR, bl+OFF_WR,
                                         nullptr, 0, nullptr, nullptr, NM,
                                         b_ur, nullptr, nullptr, rx2);

    // step 1 (h=0) is elementwise
    first_step<<<(NM*HD/4)/256, 256>>>((const float4*)fz, (const float4*)fh, (float4*)out_h);

    float* hc = out_h;
    float* hn = hA;
    for (int d = 1; d < DEPTH; ++d) {
        mma_gemm<0><<<gE, 512, SMEM_SMALL>>>(hc, HD, bh+OFF_UR, bl+OFF_UR,
                                             nullptr, 0, nullptr, nullptr, NM,
                                             nullptr, nullptr, nullptr, hU);
        gather_msgs<<<NM/4, dim3(64,4)>>>(hc, hU, rx2, bgraph, sumh, sumg);
        mma_gemm<1><<<gE, 512, SMEM_BIG>>>(sumh, HD, bh+OFF_WZB, bl+OFF_WZB,
                                           sumg, HD, bh+OFF_WHB, bl+OFF_WHB, NM,
                                           fz, fh, sumh, hn);
        float* t = hc; hc = hn; hn = t;
    }

    gather_nodes<<<NN/4, dim3(64,4)>>>(hc, agraph, nei);
    mma_gemm<2><<<gV, 512, SMEM_SMALL>>>(fnode, IND, bh+OFF_WOT, bl+OFF_WOT,
                                         nei, HD, bh+OFF_WOB, bl+OFF_WOB, NN,
                                         b_o, nullptr, mask, out_node);
}

// round 5
// speedup vs baseline: 2.2558x; 1.1435x over previous
#include <cuda_runtime.h>
#include <cuda_bf16.h>
#include <math.h>
#include <cstdint>

#define NN 35000
#define NM 80000
#define NBR 6
#define IND 128
#define HD 256
#define DEPTH 5

// ---------------- scratch (__device__ globals; no allocs) ----------------
__device__ float g_rx2 [(size_t)NM*HD];
__device__ float g_fz  [(size_t)NM*HD];
__device__ float g_fh  [(size_t)NM*HD];
__device__ float g_hU  [(size_t)NM*HD];
__device__ float g_sumh[(size_t)NM*HD];
__device__ float g_sumg[(size_t)NM*HD];
__device__ float g_hA  [(size_t)NM*HD];
__device__ float g_nei [(size_t)NN*HD];

// transposed+split weights: [N=256, K] bf16, hi and lo planes
#define OFF_WZT 0
#define OFF_WHT 32768
#define OFF_WR  65536
#define OFF_WOT 98304
#define OFF_UR  131072
#define OFF_WZB 196608
#define OFF_WHB 262144
#define OFF_WOB 327680
__device__ __nv_bfloat16 g_bh[393216];
__device__ __nv_bfloat16 g_bl[393216];

__device__ __forceinline__ float sigm(float x){ return 1.0f/(1.0f+expf(-x)); }

// ---------------- mma / ldmatrix / cp.async helpers ----------------------
__device__ __forceinline__ uint32_t smem_addr(const void* p){
    return (uint32_t)__cvta_generic_to_shared(p);
}
__device__ __forceinline__ void ldsm4(uint32_t a, uint32_t& r0, uint32_t& r1,
                                      uint32_t& r2, uint32_t& r3){
    asm volatile("ldmatrix.sync.aligned.m8n8.x4.shared.b16 {%0,%1,%2,%3}, [%4];"
                 : "=r"(r0), "=r"(r1), "=r"(r2), "=r"(r3) : "r"(a));
}
__device__ __forceinline__ void mma16816(float* c, const uint32_t* a, const uint32_t* b){
    asm volatile(
        "mma.sync.aligned.m16n8k16.row.col.f32.bf16.bf16.f32 "
        "{%0,%1,%2,%3}, {%4,%5,%6,%7}, {%8,%9}, {%0,%1,%2,%3};"
        : "+f"(c[0]), "+f"(c[1]), "+f"(c[2]), "+f"(c[3])
        : "r"(a[0]), "r"(a[1]), "r"(a[2]), "r"(a[3]), "r"(b[0]), "r"(b[1]));
}
#define CP_ASYNC16(dst, src) \
    asm volatile("cp.async.cg.shared.global [%0], [%1], 16;" :: "r"(dst), "l"(src))
#define CP_COMMIT() asm volatile("cp.async.commit_group;" ::: "memory")
#define CP_WAIT0()  asm volatile("cp.async.wait_group 0;" ::: "memory")

__device__ __forceinline__ void cvt_split8(float4 v0, float4 v1, uint4& hi, uint4& lo){
    float f[8] = {v0.x,v0.y,v0.z,v0.w,v1.x,v1.y,v1.z,v1.w};
    uint32_t hh[8], ll[8];
    #pragma unroll
    for (int j = 0; j < 8; ++j) {
        __nv_bfloat16 h = __float2bfloat16_rn(f[j]);
        float hf = __bfloat162float(h);
        __nv_bfloat16 l = __float2bfloat16_rn(f[j] - hf);
        hh[j] = (uint32_t)__bfloat16_as_ushort(h);
        ll[j] = (uint32_t)__bfloat16_as_ushort(l);
    }
    hi = make_uint4(hh[0]|(hh[1]<<16), hh[2]|(hh[3]<<16), hh[4]|(hh[5]<<16), hh[6]|(hh[7]<<16));
    lo = make_uint4(ll[0]|(ll[1]<<16), ll[2]|(ll[3]<<16), ll[4]|(ll[5]<<16), ll[6]|(ll[7]<<16));
}

// smem: 2 pipeline stages, each with A_hi/A_lo/B_hi/B_lo planes (128 x 40 bf16)
#define PADK 40
#define SM_AH 0
#define SM_AL 10240
#define SM_BH 20480
#define SM_BL 30720
#define STAGE 40960
#define SM_Z  (2*STAGE)
#define ZSTRIDE 130
#define SMEM_SMALL (2*STAGE)
#define SMEM_BIG   (2*STAGE + 128*ZSTRIDE*4)

// Pipelined phase: acc += split(A[rowBase:+128, :K]) @ B^T
// B = [256,K] bf16 hi/lo planes; uses B rows [colBase, colBase+128).
__device__ __forceinline__ void run_phase(
    const float* __restrict__ A, int K,
    const __nv_bfloat16* __restrict__ Bh, const __nv_bfloat16* __restrict__ Bl,
    float acc[2][4][4], char* sm, int tid, int rowBase, int colBase, int M)
{
    const int lane = tid & 31, wid = tid >> 5;
    const int wm = wid >> 2, wn = wid & 3;
    const int row = tid >> 2, ks = (tid & 3) << 3;     // fill: 128 rows x 32 cols
    const int grow = rowBase + row;
    const bool arowok = (grow < M);
    const int g = lane >> 3, r = lane & 7;

    const float* aptr = A + (size_t)grow*K + ks;
    const __nv_bfloat16* bhp = Bh + (size_t)(colBase + row)*K + ks;
    const __nv_bfloat16* blp = Bl + (size_t)(colBase + row)*K + ks;

    const uint32_t sb = smem_addr(sm);
    const uint32_t so = (uint32_t)(row*PADK + ks) * 2;  // byte offset within plane

    // per-warp ldmatrix base offsets (within a stage)
    const int arow = wm*32 + (g & 1)*8 + r;
    const int acol0 = (g >> 1)*8;
    const int nrow = wn*32 + (g >> 1)*8 + r;
    const int ncol0 = (g & 1)*8;

    const int nch = K >> 5;

    // ---- prologue: fill stage 0 ----
    {
        float4 v0 = make_float4(0.f,0.f,0.f,0.f), v1 = v0;
        if (arowok) { v0 = *(const float4*)aptr; v1 = *(const float4*)(aptr + 4); }
        CP_ASYNC16(sb + SM_BH + so, bhp);
        CP_ASYNC16(sb + SM_BL + so, blp);
        CP_COMMIT();
        uint4 hi, lo; cvt_split8(v0, v1, hi, lo);
        *(uint4*)(sm + SM_AH + so) = hi;
        *(uint4*)(sm + SM_AL + so) = lo;
        CP_WAIT0();
    }
    __syncthreads();

    for (int c = 0; c < nch; ++c) {
        const int buf = c & 1;
        const int nc = c + 1;
        const uint32_t st = sb + buf*STAGE;

        float4 v0, v1;
        if (nc < nch) {
            const uint32_t nst = sb + (buf ^ 1)*STAGE;
            v0 = make_float4(0.f,0.f,0.f,0.f); v1 = v0;
            if (arowok) {
                const float* p = aptr + (nc << 5);
                v0 = *(const float4*)p; v1 = *(const float4*)(p + 4);
            }
            CP_ASYNC16(nst + SM_BH + so, bhp + (nc << 5));
            CP_ASYNC16(nst + SM_BL + so, blp + (nc << 5));
            CP_COMMIT();
        }

        // ---- compute on stage buf ----
        #pragma unroll
        for (int ki = 0; ki < 2; ++ki) {
            uint32_t ah[2][4], al[2][4];
            {
                uint32_t off = (uint32_t)(arow*PADK + ki*16 + acol0) * 2;
                ldsm4(st + SM_AH + off,             ah[0][0], ah[0][1], ah[0][2], ah[0][3]);
                ldsm4(st + SM_AH + off + 16*PADK*2, ah[1][0], ah[1][1], ah[1][2], ah[1][3]);
                ldsm4(st + SM_AL + off,             al[0][0], al[0][1], al[0][2], al[0][3]);
                ldsm4(st + SM_AL + off + 16*PADK*2, al[1][0], al[1][1], al[1][2], al[1][3]);
            }
            uint32_t bhf[4][2], blf[4][2];
            {
                uint32_t off = (uint32_t)(nrow*PADK + ki*16 + ncol0) * 2;
                ldsm4(st + SM_BH + off,             bhf[0][0], bhf[0][1], bhf[1][0], bhf[1][1]);
                ldsm4(st + SM_BH + off + 16*PADK*2, bhf[2][0], bhf[2][1], bhf[3][0], bhf[3][1]);
                ldsm4(st + SM_BL + off,             blf[0][0], blf[0][1], blf[1][0], blf[1][1]);
                ldsm4(st + SM_BL + off + 16*PADK*2, blf[2][0], blf[2][1], blf[3][0], blf[3][1]);
            }
            #pragma unroll
            for (int mi = 0; mi < 2; ++mi)
                #pragma unroll
                for (int ni = 0; ni < 4; ++ni) {
                    mma16816(acc[mi][ni], ah[mi], bhf[ni]);   // hi*hi
                    mma16816(acc[mi][ni], ah[mi], blf[ni]);   // hi*lo
                    mma16816(acc[mi][ni], al[mi], bhf[ni]);   // lo*hi
                }
        }

        if (nc < nch) {
            char* nsm = sm + (buf ^ 1)*STAGE;
            uint4 hi, lo; cvt_split8(v0, v1, hi, lo);
            *(uint4*)(nsm + SM_AH + so) = hi;
            *(uint4*)(nsm + SM_AL + so) = lo;
            CP_WAIT0();
        }
        __syncthreads();
    }
}

// MODE 0: C = D1 + (e0 ? e0[col] : 0)
// MODE 1: D1 = A1@B1, D2 = A2@B2; z=sig(e0+D1), p=tanh(e1+D2);
//         C = ((1-z)*e2 + z*p), row 0 forced to 0
// MODE 2: D = A1@B1 + A2@B2; C = relu(D + e0[col]) * e2[row]
template<int MODE>
__global__ __launch_bounds__(512, 1)
void mma_gemm(const float* __restrict__ A1, int K1,
              const __nv_bfloat16* __restrict__ B1h, const __nv_bfloat16* __restrict__ B1l,
              const float* __restrict__ A2, int K2,
              const __nv_bfloat16* __restrict__ B2h, const __nv_bfloat16* __restrict__ B2l,
              int M,
              const float* __restrict__ e0, const float* __restrict__ e1,
              const float* __restrict__ e2, float* __restrict__ C)
{
    extern __shared__ char sm[];
    const int tid = threadIdx.x;
    const int colBase = (blockIdx.x & 1) << 7;
    const int rowBase = (int)(blockIdx.x >> 1) << 7;
    const int lane = tid & 31, wid = tid >> 5;
    const int wm = wid >> 2, wn = wid & 3;
    const int tq = lane >> 2, tr = lane & 3;

    float acc[2][4][4];
    #pragma unroll
    for (int i = 0; i < 2; ++i)
        #pragma unroll
        for (int j = 0; j < 4; ++j)
            #pragma unroll
            for (int q = 0; q < 4; ++q) acc[i][j][q] = 0.f;

    run_phase(A1, K1, B1h, B1l, acc, sm, tid, rowBase, colBase, M);

    if (MODE == 0) {
        #pragma unroll
        for (int mi = 0; mi < 2; ++mi)
            #pragma unroll
            for (int ni = 0; ni < 4; ++ni) {
                int gcol = colBase + wn*32 + ni*8 + tr*2;
                int r0 = rowBase + wm*32 + mi*16 + tq;
                float bx = 0.f, by = 0.f;
                if (e0) { float2 b = *(const float2*)&e0[gcol]; bx = b.x; by = b.y; }
                float2 o0 = make_float2(acc[mi][ni][0] + bx, acc[mi][ni][1] + by);
                float2 o1 = make_float2(acc[mi][ni][2] + bx, acc[mi][ni][3] + by);
                *(float2*)&C[(size_t)r0*HD + gcol]     = o0;
                *(float2*)&C[(size_t)(r0+8)*HD + gcol] = o1;
            }
    } else if (MODE == 1) {
        // stash z in smem (same-thread readback; no sync needed)
        float* zbuf = (float*)(sm + SM_Z);
        #pragma unroll
        for (int mi = 0; mi < 2; ++mi)
            #pragma unroll
            for (int ni = 0; ni < 4; ++ni) {
                int lrow = wm*32 + mi*16 + tq;
                int lcol = wn*32 + ni*8 + tr*2;
                int r0 = rowBase + lrow;
                float2 ea = *(const float2*)&e0[(size_t)r0*HD + colBase + lcol];
                float2 eb = *(const float2*)&e0[(size_t)(r0+8)*HD + colBase + lcol];
                zbuf[lrow*ZSTRIDE + lcol]       = sigm(ea.x + acc[mi][ni][0]);
                zbuf[lrow*ZSTRIDE + lcol + 1]   = sigm(ea.y + acc[mi][ni][1]);
                zbuf[(lrow+8)*ZSTRIDE + lcol]   = sigm(eb.x + acc[mi][ni][2]);
                zbuf[(lrow+8)*ZSTRIDE + lcol+1] = sigm(eb.y + acc[mi][ni][3]);
            }
        #pragma unroll
        for (int i = 0; i < 2; ++i)
            #pragma unroll
            for (int j = 0; j < 4; ++j)
                #pragma unroll
                for (int q = 0; q < 4; ++q) acc[i][j][q] = 0.f;

        run_phase(A2, K2, B2h, B2l, acc, sm, tid, rowBase, colBase, M);

        #pragma unroll
        for (int mi = 0; mi < 2; ++mi)
            #pragma unroll
            for (int ni = 0; ni < 4; ++ni) {
                int lrow = wm*32 + mi*16 + tq;
                int lcol = wn*32 + ni*8 + tr*2;
                int r0 = rowBase + lrow;
                size_t o0 = (size_t)r0*HD + colBase + lcol;
                size_t o1 = (size_t)(r0+8)*HD + colBase + lcol;
                float2 ha = *(const float2*)&e1[o0];
                float2 hb = *(const float2*)&e1[o1];
                float2 sa = *(const float2*)&e2[o0];
                float2 sb = *(const float2*)&e2[o1];
                float z0 = zbuf[lrow*ZSTRIDE + lcol];
                float z1 = zbuf[lrow*ZSTRIDE + lcol + 1];
                float z2 = zbuf[(lrow+8)*ZSTRIDE + lcol];
                float z3 = zbuf[(lrow+8)*ZSTRIDE + lcol + 1];
                float p0 = tanhf(ha.x + acc[mi][ni][0]);
                float p1 = tanhf(ha.y + acc[mi][ni][1]);
                float p2 = tanhf(hb.x + acc[mi][ni][2]);
                float p3 = tanhf(hb.y + acc[mi][ni][3]);
                float2 u0 = make_float2((1.f - z0)*sa.x + z0*p0, (1.f - z1)*sa.y + z1*p1);
                float2 u1 = make_float2((1.f - z2)*sb.x + z2*p2, (1.f - z3)*sb.y + z3*p3);
                if (r0 == 0) u0 = make_float2(0.f, 0.f);   // null message row
                *(float2*)&C[o0] = u0;
                *(float2*)&C[o1] = u1;
            }
    } else {
        run_phase(A2, K2, B2h, B2l, acc, sm, tid, rowBase, colBase, M);
        #pragma unroll
        for (int mi = 0; mi < 2; ++mi)
            #pragma unroll
            for (int ni = 0; ni < 4; ++ni) {
                int gcol = colBase + wn*32 + ni*8 + tr*2;
                int r0 = rowBase + wm*32 + mi*16 + tq;
                float2 b = *(const float2*)&e0[gcol];
                if (r0 < M) {
                    float m = e2[r0];
                    float2 o = make_float2(fmaxf(acc[mi][ni][0] + b.x, 0.f) * m,
                                           fmaxf(acc[mi][ni][1] + b.y, 0.f) * m);
                    *(float2*)&C[(size_t)r0*HD + gcol] = o;
                }
                if (r0 + 8 < M) {
                    float m = e2[r0+8];
                    float2 o = make_float2(fmaxf(acc[mi][ni][2] + b.x, 0.f) * m,
                                           fmaxf(acc[mi][ni][3] + b.y, 0.f) * m);
                    *(float2*)&C[(size_t)(r0+8)*HD + gcol] = o;
                }
            }
    }
}

// transpose + bf16 hi/lo split of W[K,256] -> out[N=256, K]
__global__ void prep_w(const float* __restrict__ W, __nv_bfloat16* __restrict__ oh,
                       __nv_bfloat16* __restrict__ ol, int K, int kshift)
{
    int i = blockIdx.x * blockDim.x + threadIdx.x;
    int k = i & (K - 1);
    int n = i >> kshift;
    float x = W[(size_t)k * HD + n];
    __nv_bfloat16 h = __float2bfloat16_rn(x);
    __nv_bfloat16 lo = __float2bfloat16_rn(x - __bfloat162float(h));
    oh[i] = h; ol[i] = lo;
}

// Step 1 degenerates (h=0): h1 = sigmoid(fz) * tanh(fh), row 0 masked.
__global__ void first_step(const float4* __restrict__ fz, const float4* __restrict__ fh,
                           float4* __restrict__ h1)
{
    size_t i = blockIdx.x*(size_t)blockDim.x + threadIdx.x;
    float4 z = fz[i], h = fh[i];
    float4 o;
    o.x = sigm(z.x)*tanhf(h.x);
    o.y = sigm(z.y)*tanhf(h.y);
    o.z = sigm(z.z)*tanhf(h.z);
    o.w = sigm(z.w)*tanhf(h.w);
    if (i < HD/4) o = make_float4(0.f,0.f,0.f,0.f);
    h1[i] = o;
}

__global__ void gather_msgs(const float* __restrict__ h, const float* __restrict__ hU,
                            const float* __restrict__ rx2, const int* __restrict__ bg,
                            float* __restrict__ sumh, float* __restrict__ sumg)
{
    __shared__ int s_nb[4][NBR];
    int e = blockIdx.x * 4 + threadIdx.y;
    if (threadIdx.x < NBR) s_nb[threadIdx.y][threadIdx.x] = bg[e*NBR + threadIdx.x];
    __syncthreads();
    int c = threadIdx.x << 2;
    size_t base = (size_t)e*HD + c;
    float4 rxv = *(const float4*)&rx2[base];
    float4 sh = make_float4(0.f,0.f,0.f,0.f);
    float4 sg = make_float4(0.f,0.f,0.f,0.f);
    #pragma unroll
    for (int j = 0; j < NBR; ++j) {
        size_t nb = (size_t)s_nb[threadIdx.y][j]*HD + c;
        float4 hv = *(const float4*)&h[nb];
        float4 hu = *(const float4*)&hU[nb];
        sh.x += hv.x; sh.y += hv.y; sh.z += hv.z; sh.w += hv.w;
        sg.x += sigm(rxv.x + hu.x) * hv.x;
        sg.y += sigm(rxv.y + hu.y) * hv.y;
        sg.z += sigm(rxv.z + hu.z) * hv.z;
        sg.w += sigm(rxv.w + hu.w) * hv.w;
    }
    *(float4*)&sumh[base] = sh;
    *(float4*)&sumg[base] = sg;
}

__global__ void gather_nodes(const float* __restrict__ h, const int* __restrict__ ag,
                             float* __restrict__ nei)
{
    __shared__ int s_nb[4][NBR];
    int v = blockIdx.x * 4 + threadIdx.y;
    if (threadIdx.x < NBR) s_nb[threadIdx.y][threadIdx.x] = ag[v*NBR + threadIdx.x];
    __syncthreads();
    int c = threadIdx.x << 2;
    float4 s = make_float4(0.f,0.f,0.f,0.f);
    #pragma unroll
    for (int j = 0; j < NBR; ++j) {
        size_t nb = (size_t)s_nb[threadIdx.y][j]*HD + c;
        float4 hv = *(const float4*)&h[nb];
        s.x += hv.x; s.y += hv.y; s.z += hv.z; s.w += hv.w;
    }
    *(float4*)&nei[(size_t)v*HD + c] = s;
}

extern "C" void kernel_launch(void* const* d_in, const int* in_sizes, int n_in,
                              void* d_out, int out_size)
{
    const float* fnode  = (const float*)d_in[0];
    const float* fmess  = (const float*)d_in[1];
    const int*   agraph = (const int*)  d_in[2];
    const int*   bgraph = (const int*)  d_in[3];
    const float* mask   = (const float*)d_in[4];
    const float* W_z    = (const float*)d_in[5];
    const float* b_z    = (const float*)d_in[6];
    const float* W_r    = (const float*)d_in[7];
    const float* U_r    = (const float*)d_in[8];
    const float* b_ur   = (const float*)d_in[9];
    const float* W_h    = (const float*)d_in[10];
    const float* b_h    = (const float*)d_in[11];
    const float* W_o    = (const float*)d_in[12];
    const float* b_o    = (const float*)d_in[13];

    float* out_node = (float*)d_out;
    float* out_h    = out_node + (size_t)NN*HD;

    float *rx2, *fz, *fh, *hU, *sumh, *sumg, *hA, *nei;
    __nv_bfloat16 *bh, *bl;
    cudaGetSymbolAddress((void**)&rx2,  g_rx2);
    cudaGetSymbolAddress((void**)&fz,   g_fz);
    cudaGetSymbolAddress((void**)&fh,   g_fh);
    cudaGetSymbolAddress((void**)&hU,   g_hU);
    cudaGetSymbolAddress((void**)&sumh, g_sumh);
    cudaGetSymbolAddress((void**)&sumg, g_sumg);
    cudaGetSymbolAddress((void**)&hA,   g_hA);
    cudaGetSymbolAddress((void**)&nei,  g_nei);
    cudaGetSymbolAddress((void**)&bh,   g_bh);
    cudaGetSymbolAddress((void**)&bl,   g_bl);

    cudaFuncSetAttribute(mma_gemm<0>, cudaFuncAttributeMaxDynamicSharedMemorySize, SMEM_SMALL);
    cudaFuncSetAttribute(mma_gemm<1>, cudaFuncAttributeMaxDynamicSharedMemorySize, SMEM_BIG);
    cudaFuncSetAttribute(mma_gemm<2>, cudaFuncAttributeMaxDynamicSharedMemorySize, SMEM_SMALL);

    // ---- weight prep: transpose + hi/lo split ----
    prep_w<<<128, 256>>>(W_z,                  bh+OFF_WZT, bl+OFF_WZT, IND, 7);
    prep_w<<<128, 256>>>(W_h,                  bh+OFF_WHT, bl+OFF_WHT, IND, 7);
    prep_w<<<128, 256>>>(W_r,                  bh+OFF_WR,  bl+OFF_WR,  IND, 7);
    prep_w<<<128, 256>>>(W_o,                  bh+OFF_WOT, bl+OFF_WOT, IND, 7);
    prep_w<<<256, 256>>>(U_r,                  bh+OFF_UR,  bl+OFF_UR,  HD, 8);
    prep_w<<<256, 256>>>(W_z + (size_t)IND*HD, bh+OFF_WZB, bl+OFF_WZB, HD, 8);
    prep_w<<<256, 256>>>(W_h + (size_t)IND*HD, bh+OFF_WHB, bl+OFF_WHB, HD, 8);
    prep_w<<<256, 256>>>(W_o + (size_t)IND*HD, bh+OFF_WOB, bl+OFF_WOB, HD, 8);

    const int gE = (NM / 128) * 2;            // 1250 (row tiles x 2 col tiles)
    const int gV = ((NN + 127) / 128) * 2;    // 548

    // loop-invariant GEMMs (bias folded via epilogue)
    mma_gemm<0><<<gE, 512, SMEM_SMALL>>>(fmess, IND, bh+OFF_WZT, bl+OFF_WZT,
                                         nullptr, 0, nullptr, nullptr, NM,
                                         b_z, nullptr, nullptr, fz);
    mma_gemm<0><<<gE, 512, SMEM_SMALL>>>(fmess, IND, bh+OFF_WHT, bl+OFF_WHT,
                                         nullptr, 0, nullptr, nullptr, NM,
                                         b_h, nullptr, nullptr, fh);
    mma_gemm<0><<<gE, 512, SMEM_SMALL>>>(fmess, IND, bh+OFF_WR, bl+OFF_WR,
                                         nullptr, 0, nullptr, nullptr, NM,
                                         b_ur, nullptr, nullptr, rx2);

    // step 1 (h=0) is elementwise
    first_step<<<(NM*HD/4)/256, 256>>>((const float4*)fz, (const float4*)fh, (float4*)out_h);

    float* hc = out_h;
    float* hn = hA;
    for (int d = 1; d < DEPTH; ++d) {
        mma_gemm<0><<<gE, 512, SMEM_SMALL>>>(hc, HD, bh+OFF_UR, bl+OFF_UR,
                                             nullptr, 0, nullptr, nullptr, NM,
                                             nullptr, nullptr, nullptr, hU);
        gather_msgs<<<NM/4, dim3(64,4)>>>(hc, hU, rx2, bgraph, sumh, sumg);
        mma_gemm<1><<<gE, 512, SMEM_BIG>>>(sumh, HD, bh+OFF_WZB, bl+OFF_WZB,
                                           sumg, HD, bh+OFF_WHB, bl+OFF_WHB, NM,
                                           fz, fh, sumh, hn);
        float* t = hc; hc = hn; hn = t;
    }

    gather_nodes<<<NN/4, dim3(64,4)>>>(hc, agraph, nei);
    mma_gemm<2><<<gV, 512, SMEM_SMALL>>>(fnode, IND, bh+OFF_WOT, bl+OFF_WOT,
                                         nei, HD, bh+OFF_WOB, bl+OFF_WOB, NN,
                                         b_o, nullptr, mask, out_node);
}